// round 3
// baseline (speedup 1.0000x reference)
#include <cuda_runtime.h>

#define N_NODES 200000
#define N_EDGES 6400000
#define HIDDEN  200
#define NHID    6

#define TM      64          // rows per block
#define NPAIR   32          // TM/2 row-pairs
#define PSTR    36          // row-pair stride (float2) -> 72 floats, padded vs 32
#define THREADS 320         // 8 row-groups x 40 col-groups
#define KSLAB   20
#define NSLAB   (HIDDEN / KSLAB)   // 10

// smem layout (bytes)
#define X_BYTES   (2 * HIDDEN * PSTR * 8)       // 115200
#define W_BYTES   (2 * KSLAB * HIDDEN * 4)      // 32000
#define SMEM_BYTES (X_BYTES + W_BYTES + 64*4 + 5*64*4)  // 148736

__device__ float g_agg[N_NODES];

// ---------------- phase A: zero the aggregation buffer ----------------
__global__ void k_zero() {
    int i = blockIdx.x * blockDim.x + threadIdx.x;
    if (i < N_NODES) g_agg[i] = 0.0f;
}

// ---------------- phase B: edge scatter-add (atomics into L2) ----------------
// edge_index is INT32: jax coerces the requested int64 to int32 because
// jax_enable_x64 is off in the reference environment.
__global__ void k_scatter(const float* __restrict__ x, const int* __restrict__ ei) {
    int i = blockIdx.x * blockDim.x + threadIdx.x;      // quad-edge index
    if (i < N_EDGES / 4) {
        const int4 s = reinterpret_cast<const int4*>(ei)[i];
        const int4 d = reinterpret_cast<const int4*>(ei + N_EDGES)[i];
        atomicAdd(&g_agg[d.x], x[s.x]);
        atomicAdd(&g_agg[d.y], x[s.y]);
        atomicAdd(&g_agg[d.z], x[s.z]);
        atomicAdd(&g_agg[d.w], x[s.w]);
    }
}

// ---------------- helpers ----------------
__device__ __forceinline__ void cp16(void* sdst, const void* gsrc) {
    unsigned saddr = (unsigned)__cvta_generic_to_shared(sdst);
    asm volatile("cp.async.cg.shared.global [%0], [%1], 16;\n" :: "r"(saddr), "l"(gsrc));
}
__device__ __forceinline__ void cp_commit() { asm volatile("cp.async.commit_group;"); }
__device__ __forceinline__ void cp_wait1()  { asm volatile("cp.async.wait_group 1;"); }
__device__ __forceinline__ void cp_wait0()  { asm volatile("cp.async.wait_group 0;"); }

__device__ __forceinline__ unsigned long long pack2(float w) {
    unsigned long long r;
    asm("mov.b64 %0, {%1, %1};" : "=l"(r) : "f"(w));
    return r;
}
__device__ __forceinline__ void fma2(unsigned long long& acc, unsigned long long a, unsigned long long b) {
    asm("fma.rn.f32x2 %0, %1, %2, %0;" : "+l"(acc) : "l"(a), "l"(b));
}
__device__ __forceinline__ float2 unpack2(unsigned long long v) {
    float2 r;
    asm("mov.b64 {%0, %1}, %2;" : "=f"(r.x), "=f"(r.y) : "l"(v));
    return r;
}

// ---------------- phase C: fused GraphConv-scalar + 8-layer MLP + sigmoid ----------------
__global__ void __launch_bounds__(THREADS, 1) k_mlp(
    const float* __restrict__ x,
    const float* __restrict__ w_rel, const float* __restrict__ b_rel,
    const float* __restrict__ w_root,
    const float* __restrict__ w_in,  const float* __restrict__ b_in,
    const float* __restrict__ w_hid, const float* __restrict__ b_hid,
    const float* __restrict__ w_out, const float* __restrict__ b_out,
    float* __restrict__ out)
{
    extern __shared__ char smem[];
    float2* Xb0   = reinterpret_cast<float2*>(smem);                 // [HIDDEN][PSTR]
    float2* Xb1   = Xb0 + HIDDEN * PSTR;
    float*  Wb    = reinterpret_cast<float*>(smem + X_BYTES);        // [2][KSLAB*HIDDEN]
    float*  h0s   = reinterpret_cast<float*>(smem + X_BYTES + W_BYTES);   // [64]
    float*  zpart = h0s + 64;                                        // [5][64]

    const int tid = threadIdx.x;
    const int rg  = tid & 7;       // row group: rows rg*8 .. rg*8+7 (pairs rg*4..rg*4+3)
    const int cg  = tid >> 3;      // col group: cols cg, cg+40, ..., cg+160
    const int row0 = blockIdx.x * TM;

    // h0 = agg*w_rel + b_rel + x*w_root  (all 1x1 weights)
    if (tid < TM) {
        int r = row0 + tid;
        h0s[tid] = g_agg[r] * w_rel[0] + b_rel[0] + x[r] * w_root[0];
    }
    // prefetch weight slab 0 of hidden layer 0
    {
        const float* src = w_hid;   // layer 0, slab 0
        for (int c = tid; c < KSLAB * HIDDEN / 4; c += THREADS)
            cp16(Wb + c * 4, src + c * 4);
        cp_commit();
    }
    __syncthreads();

    // input layer: X0[k][pair] = relu(h0 * w_in[k] + b_in[k])
    for (int t = tid; t < HIDDEN * NPAIR; t += THREADS) {
        int k = t >> 5, p = t & 31;
        float wk = w_in[k], bk = b_in[k];
        float2 v;
        v.x = fmaxf(fmaf(h0s[2 * p],     wk, bk), 0.0f);
        v.y = fmaxf(fmaf(h0s[2 * p + 1], wk, bk), 0.0f);
        Xb0[k * PSTR + p] = v;
    }

    int cur = 0;
    for (int l = 0; l < NHID; ++l) {
        unsigned long long acc[4][5];
        #pragma unroll
        for (int rr = 0; rr < 4; ++rr)
            #pragma unroll
            for (int m = 0; m < 5; ++m) acc[rr][m] = 0ull;

        const float2* Xc = cur ? Xb1 : Xb0;
        float2*       Xn = cur ? Xb0 : Xb1;
        const float*  wl = w_hid + l * HIDDEN * HIDDEN;

        for (int s = 0; s < NSLAB; ++s) {
            __syncthreads();   // (a) buffer (s+1)&1 free for refill
            bool last = (l == NHID - 1) && (s == NSLAB - 1);
            if (!last) {
                const float* nsrc = (s < NSLAB - 1) ? (wl + (s + 1) * KSLAB * HIDDEN)
                                                    : (w_hid + (l + 1) * HIDDEN * HIDDEN);
                float* ndst = Wb + ((s + 1) & 1) * (KSLAB * HIDDEN);
                for (int c = tid; c < KSLAB * HIDDEN / 4; c += THREADS)
                    cp16(ndst + c * 4, nsrc + c * 4);
                cp_commit();
                cp_wait1();    // slab s complete (only slab s+1 may stay pending)
            } else {
                cp_wait0();
            }
            __syncthreads();   // (b) slab s visible to all

            const float* wsp = Wb + (s & 1) * (KSLAB * HIDDEN) + cg;
            const float2* xps = Xc + (size_t)s * KSLAB * PSTR + rg * 4;

            #pragma unroll
            for (int kk = 0; kk < KSLAB; ++kk) {
                ulonglong2 xa = *reinterpret_cast<const ulonglong2*>(xps + kk * PSTR);
                ulonglong2 xb = *reinterpret_cast<const ulonglong2*>(xps + kk * PSTR + 2);
                unsigned long long xr0 = xa.x, xr1 = xa.y, xr2 = xb.x, xr3 = xb.y;
                #pragma unroll
                for (int m = 0; m < 5; ++m) {
                    unsigned long long wp = pack2(wsp[kk * HIDDEN + 40 * m]);
                    fma2(acc[0][m], xr0, wp);
                    fma2(acc[1][m], xr1, wp);
                    fma2(acc[2][m], xr2, wp);
                    fma2(acc[3][m], xr3, wp);
                }
            }
        }

        // epilogue: bias + relu, store to the other X buffer
        #pragma unroll
        for (int m = 0; m < 5; ++m) {
            int j = cg + 40 * m;
            float bj = b_hid[l * HIDDEN + j];
            float2 o0 = unpack2(acc[0][m]);
            float2 o1 = unpack2(acc[1][m]);
            float2 o2 = unpack2(acc[2][m]);
            float2 o3 = unpack2(acc[3][m]);
            float4 v0 = make_float4(fmaxf(o0.x + bj, 0.f), fmaxf(o0.y + bj, 0.f),
                                    fmaxf(o1.x + bj, 0.f), fmaxf(o1.y + bj, 0.f));
            float4 v1 = make_float4(fmaxf(o2.x + bj, 0.f), fmaxf(o2.y + bj, 0.f),
                                    fmaxf(o3.x + bj, 0.f), fmaxf(o3.y + bj, 0.f));
            float2* xn = Xn + j * PSTR + rg * 4;
            *reinterpret_cast<float4*>(xn)     = v0;
            *reinterpret_cast<float4*>(xn + 2) = v1;
        }
        cur ^= 1;
    }
    __syncthreads();   // final activations ready

    // output layer: z[r] = sum_k X[k][r] * w_out[k] + b_out; out = sigmoid(z)
    {
        const float* Xf = reinterpret_cast<const float*>(cur ? Xb1 : Xb0);
        int part = tid >> 6;        // 0..4
        int r    = tid & 63;
        float sum = 0.0f;
        int k0 = part * 40;
        #pragma unroll 8
        for (int k = k0; k < k0 + 40; ++k)
            sum = fmaf(Xf[k * (2 * PSTR) + r], w_out[k], sum);
        zpart[part * 64 + r] = sum;
    }
    __syncthreads();
    if (tid < TM) {
        float z = zpart[tid] + zpart[64 + tid] + zpart[128 + tid]
                + zpart[192 + tid] + zpart[256 + tid] + b_out[0];
        out[row0 + tid] = 1.0f / (1.0f + expf(-z));
    }
}

// ---------------- launch ----------------
extern "C" void kernel_launch(void* const* d_in, const int* in_sizes, int n_in,
                              void* d_out, int out_size)
{
    const float* x      = (const float*)d_in[0];
    const int*   ei     = (const int*)d_in[1];      // int32! (jax x64 disabled)
    const float* w_rel  = (const float*)d_in[2];
    const float* b_rel  = (const float*)d_in[3];
    const float* w_root = (const float*)d_in[4];
    const float* w_in   = (const float*)d_in[5];
    const float* b_in   = (const float*)d_in[6];
    const float* w_hid  = (const float*)d_in[7];
    const float* b_hid  = (const float*)d_in[8];
    const float* w_out  = (const float*)d_in[9];
    const float* b_out  = (const float*)d_in[10];
    float*       out    = (float*)d_out;

    cudaFuncSetAttribute(k_mlp, cudaFuncAttributeMaxDynamicSharedMemorySize, SMEM_BYTES);

    k_zero<<<(N_NODES + 255) / 256, 256>>>();
    k_scatter<<<(N_EDGES / 4 + 255) / 256, 256>>>(x, ei);
    k_mlp<<<N_NODES / TM, THREADS, SMEM_BYTES>>>(
        x, w_rel, b_rel, w_root, w_in, b_in, w_hid, b_hid, w_out, b_out, out);
}

// round 5
// speedup vs baseline: 2.8270x; 2.8270x over previous
#include <cuda_runtime.h>
#include <cuda_bf16.h>
#include <cstdint>

#define N_NODES 200000
#define N_EDGES 6400000
#define HIDDEN  200
#define NHID    6
#define TM      128
#define THREADS 256
#define NCTA    ((N_NODES + TM - 1) / TM)   // 1563

#define NKC     13                  // k16 chunks (K=200 padded to 208)
#define NNT     25                  // n8 tiles (N=200)
#define NSTAGE  (NHID * NKC)        // 78
#define SLAB_B  (NNT * 32 * 16)     // 12800 bytes per (layer,kc) weight slab
#define ASTRIDE 432                 // bytes per activation row (216 bf16, conflict-free)

// smem offsets (bytes)
#define RING_OFF 0                  // 4 x SLAB_B = 51200
#define AHI_OFF  51200              // 128 x 432 = 55296
#define ALO_OFF  106496
#define BIAS_OFF 161792             // 200 f32
#define WOUT_OFF 162592             // 200 f32
#define H0_OFF   163392             // 128 f32
#define SMEM_BYTES 163904

__device__ float g_agg[N_NODES];
__device__ __align__(16) uint4 g_wimg[NHID * NKC * NNT * 32];   // 998400 B

// ---------------- tiny kernels ----------------
__global__ void k_zero() {
    int i = blockIdx.x * blockDim.x + threadIdx.x;
    if (i < N_NODES) g_agg[i] = 0.0f;
}

__global__ void k_scatter(const float* __restrict__ x, const int* __restrict__ ei) {
    int i = blockIdx.x * blockDim.x + threadIdx.x;
    if (i < N_EDGES / 4) {
        const int4 s = reinterpret_cast<const int4*>(ei)[i];
        const int4 d = reinterpret_cast<const int4*>(ei + N_EDGES)[i];
        atomicAdd(&g_agg[d.x], x[s.x]);
        atomicAdd(&g_agg[d.y], x[s.y]);
        atomicAdd(&g_agg[d.z], x[s.z]);
        atomicAdd(&g_agg[d.w], x[s.w]);
    }
}

__device__ __forceinline__ uint32_t packsplit(float v0, float v1, uint32_t& lo) {
    __nv_bfloat16 h0 = __float2bfloat16(v0), h1 = __float2bfloat16(v1);
    float f0 = __bfloat162float(h0), f1 = __bfloat162float(h1);
    __nv_bfloat16 l0 = __float2bfloat16(v0 - f0), l1 = __float2bfloat16(v1 - f1);
    lo = ((uint32_t)__bfloat16_as_ushort(l1) << 16) | (uint32_t)__bfloat16_as_ushort(l0);
    return ((uint32_t)__bfloat16_as_ushort(h1) << 16) | (uint32_t)__bfloat16_as_ushort(h0);
}

// Pack w_hid into per-lane mma B-fragment order:
// idx = ((l*13+kc)*25+nt)*32 + lane -> uint4 {b0hi, b1hi, b0lo, b1lo}
// b0 holds W[k=16kc+2t +{0,1}, n=8nt+g], b1 holds k+8 pair. (t=lane&3, g=lane>>2)
__global__ void k_prep(const float* __restrict__ w_hid) {
    int idx = blockIdx.x * blockDim.x + threadIdx.x;
    if (idx >= NHID * NKC * NNT * 32) return;
    int lane = idx & 31;
    int u = idx >> 5;
    int nt = u % NNT; u /= NNT;
    int kc = u % NKC; int l = u / NKC;
    int t = lane & 3, g = lane >> 2;
    int n = nt * 8 + g;
    int k0 = kc * 16 + t * 2;
    float w00 = (k0     < HIDDEN) ? w_hid[((size_t)l * HIDDEN + k0    ) * HIDDEN + n] : 0.f;
    float w01 = (k0 + 1 < HIDDEN) ? w_hid[((size_t)l * HIDDEN + k0 + 1) * HIDDEN + n] : 0.f;
    float w10 = (k0 + 8 < HIDDEN) ? w_hid[((size_t)l * HIDDEN + k0 + 8) * HIDDEN + n] : 0.f;
    float w11 = (k0 + 9 < HIDDEN) ? w_hid[((size_t)l * HIDDEN + k0 + 9) * HIDDEN + n] : 0.f;
    uint4 v;
    uint32_t lo0, lo1;
    v.x = packsplit(w00, w01, lo0);
    v.y = packsplit(w10, w11, lo1);
    v.z = lo0;
    v.w = lo1;
    g_wimg[idx] = v;
}

// ---------------- asm helpers ----------------
__device__ __forceinline__ uint32_t s2u(const void* p) {
    uint32_t a;
    asm("{ .reg .u64 t; cvta.to.shared.u64 t, %1; cvt.u32.u64 %0, t; }" : "=r"(a) : "l"(p));
    return a;
}
__device__ __forceinline__ void cp16(uint32_t sdst, const void* gsrc) {
    asm volatile("cp.async.cg.shared.global [%0], [%1], 16;" :: "r"(sdst), "l"(gsrc));
}
#define CP_COMMIT() asm volatile("cp.async.commit_group;")
#define CP_WAIT2()  asm volatile("cp.async.wait_group 2;")

__device__ __forceinline__ void ldsm4(uint32_t* r, uint32_t a) {
    asm volatile("ldmatrix.sync.aligned.m8n8.x4.shared.b16 {%0,%1,%2,%3}, [%4];"
        : "=r"(r[0]), "=r"(r[1]), "=r"(r[2]), "=r"(r[3]) : "r"(a));
}
__device__ __forceinline__ uint4 lds128(uint32_t a) {
    uint4 v;
    asm volatile("ld.shared.v4.u32 {%0,%1,%2,%3}, [%4];"
        : "=r"(v.x), "=r"(v.y), "=r"(v.z), "=r"(v.w) : "r"(a));
    return v;
}
__device__ __forceinline__ void sts32(uint32_t a, uint32_t v) {
    asm volatile("st.shared.u32 [%0], %1;" :: "r"(a), "r"(v));
}
__device__ __forceinline__ void mma16816(float* d, const uint32_t* a, uint32_t b0, uint32_t b1) {
    asm volatile("mma.sync.aligned.m16n8k16.row.col.f32.bf16.bf16.f32 "
        "{%0,%1,%2,%3}, {%4,%5,%6,%7}, {%8,%9}, {%0,%1,%2,%3};"
        : "+f"(d[0]), "+f"(d[1]), "+f"(d[2]), "+f"(d[3])
        : "r"(a[0]), "r"(a[1]), "r"(a[2]), "r"(a[3]), "r"(b0), "r"(b1));
}

// ---------------- fused GraphConv + MLP + sigmoid ----------------
__global__ void __launch_bounds__(THREADS, 1) k_mlp(
    const float* __restrict__ x,
    const float* __restrict__ w_rel, const float* __restrict__ b_rel,
    const float* __restrict__ w_root,
    const float* __restrict__ w_in,  const float* __restrict__ b_in,
    const float* __restrict__ b_hid,
    const float* __restrict__ w_out, const float* __restrict__ b_out,
    float* __restrict__ out)
{
    extern __shared__ char smem[];
    const uint32_t sb = s2u(smem);
    const int tid  = threadIdx.x;
    const int warp = tid >> 5;
    const int lane = tid & 31;
    const int g    = lane >> 2;
    const int t    = lane & 3;
    const int row0 = blockIdx.x * TM;

    float* biasS = reinterpret_cast<float*>(smem + BIAS_OFF);
    float* woutS = reinterpret_cast<float*>(smem + WOUT_OFF);
    float* h0S   = reinterpret_cast<float*>(smem + H0_OFF);

    // stage w_out + h0
    if (tid < HIDDEN) woutS[tid] = __ldg(w_out + tid);
    if (tid < TM) {
        int r = row0 + tid;
        float a  = (r < N_NODES) ? g_agg[r] : 0.0f;
        float xv = (r < N_NODES) ? __ldg(x + r) : 0.0f;
        h0S[tid] = a * __ldg(w_rel) + __ldg(b_rel) + xv * __ldg(w_root);
    }
    __syncthreads();

    // layer-1 activations (rank-1): A[r][k] = relu(h0[r]*w_in[k]+b_in[k]), k>=200 -> 0
    for (int i = tid; i < TM * 208; i += THREADS) {
        int r = i / 208, k = i - r * 208;
        float v = 0.0f;
        if (k < HIDDEN) v = fmaxf(fmaf(h0S[r], __ldg(w_in + k), __ldg(b_in + k)), 0.0f);
        __nv_bfloat16 hb = __float2bfloat16(v);
        __nv_bfloat16 lb = __float2bfloat16(v - __bfloat162float(hb));
        *reinterpret_cast<__nv_bfloat16*>(smem + AHI_OFF + r * ASTRIDE + k * 2) = hb;
        *reinterpret_cast<__nv_bfloat16*>(smem + ALO_OFF + r * ASTRIDE + k * 2) = lb;
    }

    // prefetch weight slabs 0..2
    #pragma unroll
    for (int ps = 0; ps < 3; ++ps) {
        const char* src = reinterpret_cast<const char*>(g_wimg) + (size_t)ps * SLAB_B;
        uint32_t dst = sb + RING_OFF + ps * SLAB_B;
        for (int c = tid; c < SLAB_B / 16; c += THREADS)
            cp16(dst + c * 16, src + c * 16);
        CP_COMMIT();
    }

    // ldmatrix per-lane address (rows warp*16 .. +15)
    const int lrow = lane & 15;
    const uint32_t aHiAddr = sb + AHI_OFF + (warp * 16 + lrow) * ASTRIDE + (lane >> 4) * 16;
    const uint32_t aLoAddr = sb + ALO_OFF + (warp * 16 + lrow) * ASTRIDE + (lane >> 4) * 16;

    float d[NNT][4];

    for (int l = 0; l < NHID; ++l) {
        #pragma unroll
        for (int nt = 0; nt < NNT; ++nt) {
            d[nt][0] = 0.f; d[nt][1] = 0.f; d[nt][2] = 0.f; d[nt][3] = 0.f;
        }

        for (int kc = 0; kc < NKC; ++kc) {
            const int st = l * NKC + kc;
            CP_WAIT2();
            __syncthreads();
            if (kc == 0 && tid < HIDDEN) biasS[tid] = __ldg(b_hid + l * HIDDEN + tid);

            uint32_t ahi[4], alo[4];
            ldsm4(ahi, aHiAddr + kc * 32);
            ldsm4(alo, aLoAddr + kc * 32);

            const uint32_t bbase = sb + RING_OFF + (st & 3) * SLAB_B + lane * 16;
            #pragma unroll
            for (int nt = 0; nt < NNT; ++nt) {
                uint4 B = lds128(bbase + nt * 512);
                mma16816(d[nt], ahi, B.x, B.y);   // hi*hi
                mma16816(d[nt], alo, B.x, B.y);   // lo*hi
                mma16816(d[nt], ahi, B.z, B.w);   // hi*lo
            }

            if (st + 3 < NSTAGE) {
                const char* src = reinterpret_cast<const char*>(g_wimg) + (size_t)(st + 3) * SLAB_B;
                uint32_t dst = sb + RING_OFF + ((st + 3) & 3) * SLAB_B;
                for (int c = tid; c < SLAB_B / 16; c += THREADS)
                    cp16(dst + c * 16, src + c * 16);
            }
            CP_COMMIT();
        }

        if (l < NHID - 1) {
            // epilogue: bias+relu, split hi/lo, store next activations (warp-private rows)
            const uint32_t off0 = (warp * 16 + g) * ASTRIDE;
            #pragma unroll
            for (int nt = 0; nt < NNT; ++nt) {
                int c0 = 8 * nt + 2 * t;
                float b0 = biasS[c0], b1 = biasS[c0 + 1];
                float v0 = fmaxf(d[nt][0] + b0, 0.f), v1 = fmaxf(d[nt][1] + b1, 0.f);
                float v2 = fmaxf(d[nt][2] + b0, 0.f), v3 = fmaxf(d[nt][3] + b1, 0.f);
                uint32_t lw0, lw1;
                uint32_t hw0 = packsplit(v0, v1, lw0);
                uint32_t hw1 = packsplit(v2, v3, lw1);
                uint32_t a0 = off0 + c0 * 2;
                uint32_t a1 = a0 + 8 * ASTRIDE;
                sts32(sb + AHI_OFF + a0, hw0);
                sts32(sb + ALO_OFF + a0, lw0);
                sts32(sb + AHI_OFF + a1, hw1);
                sts32(sb + ALO_OFF + a1, lw1);
            }
        } else {
            // final: z = sum relu(d+b)*w_out ; sigmoid
            float z0 = 0.f, z1 = 0.f;
            #pragma unroll
            for (int nt = 0; nt < NNT; ++nt) {
                int c0 = 8 * nt + 2 * t;
                float b0 = biasS[c0], b1 = biasS[c0 + 1];
                float w0 = woutS[c0], w1 = woutS[c0 + 1];
                z0 = fmaf(fmaxf(d[nt][0] + b0, 0.f), w0, z0);
                z0 = fmaf(fmaxf(d[nt][1] + b1, 0.f), w1, z0);
                z1 = fmaf(fmaxf(d[nt][2] + b0, 0.f), w0, z1);
                z1 = fmaf(fmaxf(d[nt][3] + b1, 0.f), w1, z1);
            }
            z0 += __shfl_xor_sync(0xffffffffu, z0, 1);
            z0 += __shfl_xor_sync(0xffffffffu, z0, 2);
            z1 += __shfl_xor_sync(0xffffffffu, z1, 1);
            z1 += __shfl_xor_sync(0xffffffffu, z1, 2);
            if (t == 0) {
                float bo = __ldg(b_out);
                int r0 = row0 + warp * 16 + g;
                int r1 = r0 + 8;
                if (r0 < N_NODES) out[r0] = 1.0f / (1.0f + expf(-(z0 + bo)));
                if (r1 < N_NODES) out[r1] = 1.0f / (1.0f + expf(-(z1 + bo)));
            }
        }
    }
}

// ---------------- launch ----------------
extern "C" void kernel_launch(void* const* d_in, const int* in_sizes, int n_in,
                              void* d_out, int out_size)
{
    const float* x      = (const float*)d_in[0];
    const int*   ei     = (const int*)d_in[1];      // int32 (jax x64 disabled)
    const float* w_rel  = (const float*)d_in[2];
    const float* b_rel  = (const float*)d_in[3];
    const float* w_root = (const float*)d_in[4];
    const float* w_in   = (const float*)d_in[5];
    const float* b_in   = (const float*)d_in[6];
    const float* w_hid  = (const float*)d_in[7];
    const float* b_hid  = (const float*)d_in[8];
    const float* w_out  = (const float*)d_in[9];
    const float* b_out  = (const float*)d_in[10];
    float*       out    = (float*)d_out;

    cudaFuncSetAttribute(k_mlp, cudaFuncAttributeMaxDynamicSharedMemorySize, SMEM_BYTES);

    k_prep<<<(NHID * NKC * NNT * 32 + 255) / 256, 256>>>(w_hid);
    k_zero<<<(N_NODES + 255) / 256, 256>>>();
    k_scatter<<<(N_EDGES / 4 + 255) / 256, 256>>>(x, ei);
    k_mlp<<<NCTA, THREADS, SMEM_BYTES>>>(
        x, w_rel, b_rel, w_root, w_in, b_in, b_hid, w_out, b_out, out);
}